// round 1
// baseline (speedup 1.0000x reference)
#include <cuda_runtime.h>
#include <cuda_bf16.h>

// Problem constants
#define BB 4
#define TT 2048
#define CC 1024
#define HH 16
#define DD 64
#define M_ROWS (BB * TT)          // 8192
#define N_QKV  (3 * CC)           // 3072

// Scratch (device globals — allocation-free)
__device__ float g_qkv[(size_t)M_ROWS * N_QKV];   // [B*T, 3C]  ~100.7 MB
__device__ float g_y[(size_t)M_ROWS * CC];        // [B*T, C]   ~33.6 MB

// ---------------------------------------------------------------------------
// SGEMM with bias:  C[M,N] = A[M,K] @ B[K,N] + bias[N]
// 128x128 block tile, BK=8, 8x8 per-thread register tile, 256 threads.
// ---------------------------------------------------------------------------
#define GBM 128
#define GBN 128
#define GBK 8
#define GTM 8
#define GTN 8

__global__ __launch_bounds__(256)
void sgemm_bias_kernel(const float* __restrict__ A,
                       const float* __restrict__ B,
                       const float* __restrict__ bias,
                       float* __restrict__ C,
                       int M, int N, int K)
{
    __shared__ float As[GBK][GBM];
    __shared__ float Bs[GBK][GBN];

    const int tid = threadIdx.x;
    const int cRow = blockIdx.y;
    const int cCol = blockIdx.x;

    const int threadRow = tid / (GBN / GTN);   // 0..15
    const int threadCol = tid % (GBN / GTN);   // 0..15

    A += (size_t)cRow * GBM * K;
    B += (size_t)cCol * GBN;
    C += (size_t)cRow * GBM * N + (size_t)cCol * GBN;

    // A tile: 128x8 floats = 256 float4 → one per thread
    const int aRow = tid >> 1;            // 0..127
    const int aCol = (tid & 1) * 4;       // 0 or 4
    // B tile: 8x128 floats = 256 float4 → one per thread
    const int bRow = tid >> 5;            // 0..7
    const int bCol = (tid & 31) * 4;      // 0..124

    float acc[GTM][GTN];
    #pragma unroll
    for (int i = 0; i < GTM; i++)
        #pragma unroll
        for (int j = 0; j < GTN; j++) acc[i][j] = 0.0f;

    float regM[GTM], regN[GTN];

    for (int k0 = 0; k0 < K; k0 += GBK) {
        float4 av = *(const float4*)&A[(size_t)aRow * K + k0 + aCol];
        As[aCol + 0][aRow] = av.x;
        As[aCol + 1][aRow] = av.y;
        As[aCol + 2][aRow] = av.z;
        As[aCol + 3][aRow] = av.w;
        float4 bv = *(const float4*)&B[(size_t)(k0 + bRow) * N + bCol];
        *(float4*)&Bs[bRow][bCol] = bv;
        __syncthreads();

        #pragma unroll
        for (int k = 0; k < GBK; k++) {
            #pragma unroll
            for (int i = 0; i < GTM; i += 4) {
                float4 t = *(const float4*)&As[k][threadRow * GTM + i];
                regM[i] = t.x; regM[i+1] = t.y; regM[i+2] = t.z; regM[i+3] = t.w;
            }
            #pragma unroll
            for (int j = 0; j < GTN; j += 4) {
                float4 t = *(const float4*)&Bs[k][threadCol * GTN + j];
                regN[j] = t.x; regN[j+1] = t.y; regN[j+2] = t.z; regN[j+3] = t.w;
            }
            #pragma unroll
            for (int i = 0; i < GTM; i++)
                #pragma unroll
                for (int j = 0; j < GTN; j++)
                    acc[i][j] += regM[i] * regN[j];
        }
        __syncthreads();
    }

    #pragma unroll
    for (int i = 0; i < GTM; i++) {
        int row = threadRow * GTM + i;
        #pragma unroll
        for (int j = 0; j < GTN; j += 4) {
            int col = threadCol * GTN + j;
            int gcol = cCol * GBN + col;
            float4 o;
            o.x = acc[i][j + 0] + bias[gcol + 0];
            o.y = acc[i][j + 1] + bias[gcol + 1];
            o.z = acc[i][j + 2] + bias[gcol + 2];
            o.w = acc[i][j + 3] + bias[gcol + 3];
            *(float4*)&C[(size_t)row * N + col] = o;
        }
    }
}

// ---------------------------------------------------------------------------
// Causal flash attention over the fused qkv buffer.
// One thread per query row; q and o live in registers.
// K/V tiles (64 x 64 fp32 each) staged in shared memory; broadcast reads.
// qkv layout: [B, T, 3C]; q at +h*D, k at +C+h*D, v at +2C+h*D.
// Output y: [B, T, C] at channel h*D.
// ---------------------------------------------------------------------------
#define AT_BM 128   // query rows per block (= blockDim.x)
#define AT_BN 64    // keys per smem tile

__global__ __launch_bounds__(AT_BM)
void attn_kernel(const float* __restrict__ qkv, float* __restrict__ y)
{
    const int bh = blockIdx.y;            // 0..B*H-1
    const int b  = bh / HH;
    const int h  = bh % HH;
    const int tid = threadIdx.x;
    const int t  = blockIdx.x * AT_BM + tid;   // this thread's query index

    __shared__ float Ks[AT_BN][DD];
    __shared__ float Vs[AT_BN][DD];

    const float scale = 0.125f;  // 1/sqrt(64)

    const float* qp = qkv + ((size_t)(b * TT + t)) * N_QKV + h * DD;
    float q[DD];
    #pragma unroll
    for (int d = 0; d < DD; d += 4) {
        float4 v4 = *(const float4*)&qp[d];
        q[d + 0] = v4.x * scale;
        q[d + 1] = v4.y * scale;
        q[d + 2] = v4.z * scale;
        q[d + 3] = v4.w * scale;
    }

    float o[DD];
    #pragma unroll
    for (int d = 0; d < DD; d++) o[d] = 0.0f;
    float m = -1e30f, l = 0.0f;

    const int kmax = blockIdx.x * AT_BM + AT_BM;  // exclusive upper key bound for block

    for (int k0 = 0; k0 < kmax; k0 += AT_BN) {
        // Cooperative K/V tile load: 128 threads, each loads half a row (32 floats) of K and V.
        {
            int r  = tid >> 1;
            int c0 = (tid & 1) * 32;
            const float* kp = qkv + ((size_t)(b * TT + k0 + r)) * N_QKV + CC + h * DD + c0;
            const float* vp = kp + CC;
            #pragma unroll
            for (int c = 0; c < 32; c += 4) {
                *(float4*)&Ks[r][c0 + c] = *(const float4*)&kp[c];
                *(float4*)&Vs[r][c0 + c] = *(const float4*)&vp[c];
            }
        }
        __syncthreads();

        int jmax = t - k0 + 1;
        if (jmax > AT_BN) jmax = AT_BN;

        for (int j = 0; j < jmax; j++) {
            float s = 0.0f;
            #pragma unroll
            for (int d = 0; d < DD; d += 4) {
                float4 kk = *(const float4*)&Ks[j][d];
                s += q[d + 0] * kk.x;
                s += q[d + 1] * kk.y;
                s += q[d + 2] * kk.z;
                s += q[d + 3] * kk.w;
            }
            float mnew = fmaxf(m, s);
            float corr = __expf(m - mnew);
            float p    = __expf(s - mnew);
            l = l * corr + p;
            m = mnew;
            #pragma unroll
            for (int d = 0; d < DD; d += 4) {
                float4 vv = *(const float4*)&Vs[j][d];
                o[d + 0] = o[d + 0] * corr + p * vv.x;
                o[d + 1] = o[d + 1] * corr + p * vv.y;
                o[d + 2] = o[d + 2] * corr + p * vv.z;
                o[d + 3] = o[d + 3] * corr + p * vv.w;
            }
        }
        __syncthreads();
    }

    const float inv = 1.0f / l;
    float* yp = y + ((size_t)(b * TT + t)) * CC + h * DD;
    #pragma unroll
    for (int d = 0; d < DD; d += 4) {
        float4 ov;
        ov.x = o[d + 0] * inv;
        ov.y = o[d + 1] * inv;
        ov.z = o[d + 2] * inv;
        ov.w = o[d + 3] * inv;
        *(float4*)&yp[d] = ov;
    }
}

// ---------------------------------------------------------------------------
// Launch
// ---------------------------------------------------------------------------
extern "C" void kernel_launch(void* const* d_in, const int* in_sizes, int n_in,
                              void* d_out, int out_size)
{
    const float* x      = (const float*)d_in[0];
    const float* w_qkv  = (const float*)d_in[1];
    const float* b_qkv  = (const float*)d_in[2];
    const float* w_proj = (const float*)d_in[3];
    const float* b_proj = (const float*)d_in[4];
    float* out = (float*)d_out;

    float* qkv = nullptr;
    float* y   = nullptr;
    cudaGetSymbolAddress((void**)&qkv, g_qkv);
    cudaGetSymbolAddress((void**)&y,   g_y);

    // 1) QKV projection: [8192,1024] @ [1024,3072] + bias
    {
        dim3 grid(N_QKV / GBN, M_ROWS / GBM);   // (24, 64)
        sgemm_bias_kernel<<<grid, 256>>>(x, w_qkv, b_qkv, qkv, M_ROWS, N_QKV, CC);
    }

    // 2) Causal attention
    {
        dim3 grid(TT / AT_BM, BB * HH);         // (16, 64)
        attn_kernel<<<grid, AT_BM>>>(qkv, y);
    }

    // 3) Output projection: [8192,1024] @ [1024,1024] + bias
    {
        dim3 grid(CC / GBN, M_ROWS / GBM);      // (8, 64)
        sgemm_bias_kernel<<<grid, 256>>>(y, w_proj, b_proj, out, M_ROWS, CC, CC);
    }
}

// round 3
// speedup vs baseline: 1.3758x; 1.3758x over previous
#include <cuda_runtime.h>
#include <cuda_bf16.h>

// Problem constants
#define BB 4
#define TT 2048
#define CC 1024
#define HH 16
#define DD 64
#define M_ROWS (BB * TT)          // 8192
#define N_QKV  (3 * CC)           // 3072

// Scratch (device globals — allocation-free)
__device__ float g_qkv[(size_t)M_ROWS * N_QKV];   // [B*T, 3C]
__device__ float g_y[(size_t)M_ROWS * CC];        // [B*T, C]

// ---------------------------------------------------------------------------
// TF32 tensor-core GEMM with bias:  C[M,N] = A[M,K] @ B[K,N] + bias[N]
// 128x128x16 block tile, 8 warps, 64x32 warp tile, m16n8k8 tf32 mma.
// ---------------------------------------------------------------------------
#define TBM 128
#define TBN 128
#define TBK 16

__device__ __forceinline__ unsigned f2tf32(float x) {
    unsigned r;
    asm("cvt.rna.tf32.f32 %0, %1;" : "=r"(r) : "f"(x));
    return r;
}

__device__ __forceinline__ void mma_tf32(float* c, const unsigned* a, const unsigned* b) {
    asm volatile(
        "mma.sync.aligned.m16n8k8.row.col.f32.tf32.tf32.f32 "
        "{%0,%1,%2,%3}, {%4,%5,%6,%7}, {%8,%9}, {%0,%1,%2,%3};"
        : "+f"(c[0]), "+f"(c[1]), "+f"(c[2]), "+f"(c[3])
        : "r"(a[0]), "r"(a[1]), "r"(a[2]), "r"(a[3]),
          "r"(b[0]), "r"(b[1]));
}

#define AS_STRIDE (TBK + 4)    // 20 words  -> conflict-free fragment reads
#define BS_STRIDE (TBN + 8)    // 136 words -> conflict-free fragment reads

__global__ __launch_bounds__(256, 2)
void gemm_tf32_bias(const float* __restrict__ A,
                    const float* __restrict__ B,
                    const float* __restrict__ bias,
                    float* __restrict__ C,
                    int M, int N, int K)
{
    __shared__ unsigned As[TBM][AS_STRIDE];
    __shared__ unsigned Bs[TBK][BS_STRIDE];

    const int tid  = threadIdx.x;
    const int warp = tid >> 5;
    const int lane = tid & 31;
    const int wm = (warp >> 2) * 64;     // warp row offset in block
    const int wn = (warp & 3) * 32;      // warp col offset in block
    const int lr = lane >> 2;            // 0..7
    const int lc = lane & 3;             // 0..3

    const int blockM = blockIdx.y * TBM;
    const int blockN = blockIdx.x * TBN;

    // Global-load coordinates (each thread: 2 float4 of A, 2 float4 of B per tile)
    const int a0r = tid >> 2,          a0c = (tid & 3) * 4;          // ids 0..255
    const int a1r = (tid + 256) >> 2,  a1c = a0c;                    // ids 256..511
    const int b0r = tid >> 5,          b0c = (tid & 31) * 4;
    const int b1r = b0r + 8,           b1c = b0c;

    const float* Ag = A + (size_t)blockM * K;
    const float* Bg = B + blockN;

    float acc[4][4][4];
    #pragma unroll
    for (int i = 0; i < 4; i++)
        #pragma unroll
        for (int j = 0; j < 4; j++)
            #pragma unroll
            for (int r = 0; r < 4; r++) acc[i][j][r] = 0.0f;

    float4 ra0, ra1, rb0, rb1;

    // Prologue: load tile 0
    ra0 = *(const float4*)&Ag[(size_t)a0r * K + a0c];
    ra1 = *(const float4*)&Ag[(size_t)a1r * K + a1c];
    rb0 = *(const float4*)&Bg[(size_t)b0r * N + b0c];
    rb1 = *(const float4*)&Bg[(size_t)b1r * N + b1c];

    for (int k0 = 0; k0 < K; k0 += TBK) {
        // Store current tile to smem (with tf32 rounding)
        {
            uint4 t;
            t.x = f2tf32(ra0.x); t.y = f2tf32(ra0.y); t.z = f2tf32(ra0.z); t.w = f2tf32(ra0.w);
            *(uint4*)&As[a0r][a0c] = t;
            t.x = f2tf32(ra1.x); t.y = f2tf32(ra1.y); t.z = f2tf32(ra1.z); t.w = f2tf32(ra1.w);
            *(uint4*)&As[a1r][a1c] = t;
            t.x = f2tf32(rb0.x); t.y = f2tf32(rb0.y); t.z = f2tf32(rb0.z); t.w = f2tf32(rb0.w);
            *(uint4*)&Bs[b0r][b0c] = t;
            t.x = f2tf32(rb1.x); t.y = f2tf32(rb1.y); t.z = f2tf32(rb1.z); t.w = f2tf32(rb1.w);
            *(uint4*)&Bs[b1r][b1c] = t;
        }
        __syncthreads();

        // Prefetch next tile while computing this one
        const int kn = k0 + TBK;
        if (kn < K) {
            ra0 = *(const float4*)&Ag[(size_t)a0r * K + kn + a0c];
            ra1 = *(const float4*)&Ag[(size_t)a1r * K + kn + a1c];
            rb0 = *(const float4*)&Bg[(size_t)(kn + b0r) * N + b0c];
            rb1 = *(const float4*)&Bg[(size_t)(kn + b1r) * N + b1c];
        }

        #pragma unroll
        for (int kk = 0; kk < TBK; kk += 8) {
            unsigned af[4][4], bf[4][2];
            #pragma unroll
            for (int mt = 0; mt < 4; mt++) {
                int row = wm + mt * 16 + lr;
                int col = kk + lc;
                // PTX m16n8k8 tf32 A-fragment order:
                //   a0=(r,c)  a1=(r+8,c)  a2=(r,c+4)  a3=(r+8,c+4)
                af[mt][0] = As[row][col];
                af[mt][1] = As[row + 8][col];
                af[mt][2] = As[row][col + 4];
                af[mt][3] = As[row + 8][col + 4];
            }
            #pragma unroll
            for (int nt = 0; nt < 4; nt++) {
                int row = kk + lc;
                int col = wn + nt * 8 + lr;
                bf[nt][0] = Bs[row][col];
                bf[nt][1] = Bs[row + 4][col];
            }
            #pragma unroll
            for (int mt = 0; mt < 4; mt++)
                #pragma unroll
                for (int nt = 0; nt < 4; nt++)
                    mma_tf32(acc[mt][nt], af[mt], bf[nt]);
        }
        __syncthreads();
    }

    // Epilogue: bias add + store (float2 per fragment row)
    #pragma unroll
    for (int mt = 0; mt < 4; mt++) {
        #pragma unroll
        for (int nt = 0; nt < 4; nt++) {
            int r0 = blockM + wm + mt * 16 + lr;
            int c0 = blockN + wn + nt * 8 + lc * 2;
            float bx = bias[c0], by = bias[c0 + 1];
            float2 v0 = make_float2(acc[mt][nt][0] + bx, acc[mt][nt][1] + by);
            float2 v1 = make_float2(acc[mt][nt][2] + bx, acc[mt][nt][3] + by);
            *(float2*)&C[(size_t)r0 * N + c0]       = v0;
            *(float2*)&C[(size_t)(r0 + 8) * N + c0] = v1;
        }
    }
}

// ---------------------------------------------------------------------------
// Causal flash attention (fp32, unchanged — known correct).
// ---------------------------------------------------------------------------
#define AT_BM 128
#define AT_BN 64

__global__ __launch_bounds__(AT_BM)
void attn_kernel(const float* __restrict__ qkv, float* __restrict__ y)
{
    const int bh = blockIdx.y;
    const int b  = bh / HH;
    const int h  = bh % HH;
    const int tid = threadIdx.x;
    const int t  = blockIdx.x * AT_BM + tid;

    __shared__ float Ks[AT_BN][DD];
    __shared__ float Vs[AT_BN][DD];

    const float scale = 0.125f;  // 1/sqrt(64)

    const float* qp = qkv + ((size_t)(b * TT + t)) * N_QKV + h * DD;
    float q[DD];
    #pragma unroll
    for (int d = 0; d < DD; d += 4) {
        float4 v4 = *(const float4*)&qp[d];
        q[d + 0] = v4.x * scale;
        q[d + 1] = v4.y * scale;
        q[d + 2] = v4.z * scale;
        q[d + 3] = v4.w * scale;
    }

    float o[DD];
    #pragma unroll
    for (int d = 0; d < DD; d++) o[d] = 0.0f;
    float m = -1e30f, l = 0.0f;

    const int kmax = blockIdx.x * AT_BM + AT_BM;

    for (int k0 = 0; k0 < kmax; k0 += AT_BN) {
        {
            int r  = tid >> 1;
            int c0 = (tid & 1) * 32;
            const float* kp = qkv + ((size_t)(b * TT + k0 + r)) * N_QKV + CC + h * DD + c0;
            const float* vp = kp + CC;
            #pragma unroll
            for (int c = 0; c < 32; c += 4) {
                *(float4*)&Ks[r][c0 + c] = *(const float4*)&kp[c];
                *(float4*)&Vs[r][c0 + c] = *(const float4*)&vp[c];
            }
        }
        __syncthreads();

        int jmax = t - k0 + 1;
        if (jmax > AT_BN) jmax = AT_BN;

        for (int j = 0; j < jmax; j++) {
            float s = 0.0f;
            #pragma unroll
            for (int d = 0; d < DD; d += 4) {
                float4 kk = *(const float4*)&Ks[j][d];
                s += q[d + 0] * kk.x;
                s += q[d + 1] * kk.y;
                s += q[d + 2] * kk.z;
                s += q[d + 3] * kk.w;
            }
            float mnew = fmaxf(m, s);
            float corr = __expf(m - mnew);
            float p    = __expf(s - mnew);
            l = l * corr + p;
            m = mnew;
            #pragma unroll
            for (int d = 0; d < DD; d += 4) {
                float4 vv = *(const float4*)&Vs[j][d];
                o[d + 0] = o[d + 0] * corr + p * vv.x;
                o[d + 1] = o[d + 1] * corr + p * vv.y;
                o[d + 2] = o[d + 2] * corr + p * vv.z;
                o[d + 3] = o[d + 3] * corr + p * vv.w;
            }
        }
        __syncthreads();
    }

    const float inv = 1.0f / l;
    float* yp = y + ((size_t)(b * TT + t)) * CC + h * DD;
    #pragma unroll
    for (int d = 0; d < DD; d += 4) {
        float4 ov;
        ov.x = o[d + 0] * inv;
        ov.y = o[d + 1] * inv;
        ov.z = o[d + 2] * inv;
        ov.w = o[d + 3] * inv;
        *(float4*)&yp[d] = ov;
    }
}

// ---------------------------------------------------------------------------
// Launch
// ---------------------------------------------------------------------------
extern "C" void kernel_launch(void* const* d_in, const int* in_sizes, int n_in,
                              void* d_out, int out_size)
{
    const float* x      = (const float*)d_in[0];
    const float* w_qkv  = (const float*)d_in[1];
    const float* b_qkv  = (const float*)d_in[2];
    const float* w_proj = (const float*)d_in[3];
    const float* b_proj = (const float*)d_in[4];
    float* out = (float*)d_out;

    float* qkv = nullptr;
    float* y   = nullptr;
    cudaGetSymbolAddress((void**)&qkv, g_qkv);
    cudaGetSymbolAddress((void**)&y,   g_y);

    // 1) QKV projection: [8192,1024] @ [1024,3072] + bias
    {
        dim3 grid(N_QKV / TBN, M_ROWS / TBM);   // (24, 64)
        gemm_tf32_bias<<<grid, 256>>>(x, w_qkv, b_qkv, qkv, M_ROWS, N_QKV, CC);
    }

    // 2) Causal attention
    {
        dim3 grid(TT / AT_BM, BB * HH);         // (16, 64)
        attn_kernel<<<grid, AT_BM>>>(qkv, y);
    }

    // 3) Output projection: [8192,1024] @ [1024,1024] + bias
    {
        dim3 grid(CC / TBN, M_ROWS / TBM);      // (8, 64)
        gemm_tf32_bias<<<grid, 256>>>(y, w_proj, b_proj, out, M_ROWS, CC, CC);
    }
}

// round 4
// speedup vs baseline: 3.7699x; 2.7400x over previous
#include <cuda_runtime.h>
#include <cuda_bf16.h>

// Problem constants
#define BB 4
#define TT 2048
#define CC 1024
#define HH 16
#define DD 64
#define M_ROWS (BB * TT)          // 8192
#define N_QKV  (3 * CC)           // 3072

// Scratch (device globals — allocation-free)
__device__ float g_qkv[(size_t)M_ROWS * N_QKV];   // [B*T, 3C]
__device__ float g_y[(size_t)M_ROWS * CC];        // [B*T, C]

__device__ __forceinline__ unsigned f2tf32(float x) {
    unsigned r;
    asm("cvt.rna.tf32.f32 %0, %1;" : "=r"(r) : "f"(x));
    return r;
}

__device__ __forceinline__ float exp2a(float x) {
    float r;
    asm("ex2.approx.ftz.f32 %0, %1;" : "=f"(r) : "f"(x));
    return r;
}

__device__ __forceinline__ void mma_tf32(float* c, const unsigned* a, const unsigned* b) {
    asm volatile(
        "mma.sync.aligned.m16n8k8.row.col.f32.tf32.tf32.f32 "
        "{%0,%1,%2,%3}, {%4,%5,%6,%7}, {%8,%9}, {%0,%1,%2,%3};"
        : "+f"(c[0]), "+f"(c[1]), "+f"(c[2]), "+f"(c[3])
        : "r"(a[0]), "r"(a[1]), "r"(a[2]), "r"(a[3]),
          "r"(b[0]), "r"(b[1]));
}

// ---------------------------------------------------------------------------
// TF32 tensor-core GEMM with bias (unchanged, verified in R3)
// ---------------------------------------------------------------------------
#define TBM 128
#define TBN 128
#define TBK 16
#define AS_STRIDE (TBK + 4)
#define BS_STRIDE (TBN + 8)

__global__ __launch_bounds__(256, 2)
void gemm_tf32_bias(const float* __restrict__ A,
                    const float* __restrict__ B,
                    const float* __restrict__ bias,
                    float* __restrict__ C,
                    int M, int N, int K)
{
    __shared__ unsigned As[TBM][AS_STRIDE];
    __shared__ unsigned Bs[TBK][BS_STRIDE];

    const int tid  = threadIdx.x;
    const int warp = tid >> 5;
    const int lane = tid & 31;
    const int wm = (warp >> 2) * 64;
    const int wn = (warp & 3) * 32;
    const int lr = lane >> 2;
    const int lc = lane & 3;

    const int blockM = blockIdx.y * TBM;
    const int blockN = blockIdx.x * TBN;

    const int a0r = tid >> 2,          a0c = (tid & 3) * 4;
    const int a1r = (tid + 256) >> 2,  a1c = a0c;
    const int b0r = tid >> 5,          b0c = (tid & 31) * 4;
    const int b1r = b0r + 8,           b1c = b0c;

    const float* Ag = A + (size_t)blockM * K;
    const float* Bg = B + blockN;

    float acc[4][4][4];
    #pragma unroll
    for (int i = 0; i < 4; i++)
        #pragma unroll
        for (int j = 0; j < 4; j++)
            #pragma unroll
            for (int r = 0; r < 4; r++) acc[i][j][r] = 0.0f;

    float4 ra0, ra1, rb0, rb1;

    ra0 = *(const float4*)&Ag[(size_t)a0r * K + a0c];
    ra1 = *(const float4*)&Ag[(size_t)a1r * K + a1c];
    rb0 = *(const float4*)&Bg[(size_t)b0r * N + b0c];
    rb1 = *(const float4*)&Bg[(size_t)b1r * N + b1c];

    for (int k0 = 0; k0 < K; k0 += TBK) {
        {
            uint4 t;
            t.x = f2tf32(ra0.x); t.y = f2tf32(ra0.y); t.z = f2tf32(ra0.z); t.w = f2tf32(ra0.w);
            *(uint4*)&As[a0r][a0c] = t;
            t.x = f2tf32(ra1.x); t.y = f2tf32(ra1.y); t.z = f2tf32(ra1.z); t.w = f2tf32(ra1.w);
            *(uint4*)&As[a1r][a1c] = t;
            t.x = f2tf32(rb0.x); t.y = f2tf32(rb0.y); t.z = f2tf32(rb0.z); t.w = f2tf32(rb0.w);
            *(uint4*)&Bs[b0r][b0c] = t;
            t.x = f2tf32(rb1.x); t.y = f2tf32(rb1.y); t.z = f2tf32(rb1.z); t.w = f2tf32(rb1.w);
            *(uint4*)&Bs[b1r][b1c] = t;
        }
        __syncthreads();

        const int kn = k0 + TBK;
        if (kn < K) {
            ra0 = *(const float4*)&Ag[(size_t)a0r * K + kn + a0c];
            ra1 = *(const float4*)&Ag[(size_t)a1r * K + kn + a1c];
            rb0 = *(const float4*)&Bg[(size_t)(kn + b0r) * N + b0c];
            rb1 = *(const float4*)&Bg[(size_t)(kn + b1r) * N + b1c];
        }

        #pragma unroll
        for (int kk = 0; kk < TBK; kk += 8) {
            unsigned af[4][4], bf[4][2];
            #pragma unroll
            for (int mt = 0; mt < 4; mt++) {
                int row = wm + mt * 16 + lr;
                int col = kk + lc;
                af[mt][0] = As[row][col];
                af[mt][1] = As[row + 8][col];
                af[mt][2] = As[row][col + 4];
                af[mt][3] = As[row + 8][col + 4];
            }
            #pragma unroll
            for (int nt = 0; nt < 4; nt++) {
                int row = kk + lc;
                int col = wn + nt * 8 + lr;
                bf[nt][0] = Bs[row][col];
                bf[nt][1] = Bs[row + 4][col];
            }
            #pragma unroll
            for (int mt = 0; mt < 4; mt++)
                #pragma unroll
                for (int nt = 0; nt < 4; nt++)
                    mma_tf32(acc[mt][nt], af[mt], bf[nt]);
        }
        __syncthreads();
    }

    #pragma unroll
    for (int mt = 0; mt < 4; mt++) {
        #pragma unroll
        for (int nt = 0; nt < 4; nt++) {
            int r0 = blockM + wm + mt * 16 + lr;
            int c0 = blockN + wn + nt * 8 + lc * 2;
            float bx = bias[c0], by = bias[c0 + 1];
            float2 v0 = make_float2(acc[mt][nt][0] + bx, acc[mt][nt][1] + by);
            float2 v1 = make_float2(acc[mt][nt][2] + bx, acc[mt][nt][3] + by);
            *(float2*)&C[(size_t)r0 * N + c0]       = v0;
            *(float2*)&C[(size_t)(r0 + 8) * N + c0] = v1;
        }
    }
}

// ---------------------------------------------------------------------------
// TF32 MMA causal flash attention.
// Block: 64 queries (4 warps x 16 rows), 64-key tiles.
// K/V in natural [key][d] smem (stride 68 -> conflict-free fragment reads).
// Q fragments register-resident. P round-trips through smem aliased onto K.
// ---------------------------------------------------------------------------
#define KV_STRIDE 68

__global__ __launch_bounds__(128, 2)
void attn_mma(const float* __restrict__ qkv, float* __restrict__ y)
{
    __shared__ unsigned Kn[64][KV_STRIDE];   // K tile [key][d]
    __shared__ unsigned Vs[64][KV_STRIDE];   // V tile [key][d]

    const int tid  = threadIdx.x;
    const int warp = tid >> 5;
    const int lane = tid & 31;
    const int lr = lane >> 2;    // 0..7
    const int lc = lane & 3;     // 0..3

    const int qb = blockIdx.x;               // query block (0..31)
    const int bh = blockIdx.y;               // b*H + h
    const int b  = bh >> 4;
    const int h  = bh & 15;
    const int q0 = qb * 64;

    // P buffer: per-warp 16 x 64 region aliased onto Kn (dead after S-mma)
    unsigned (*Ps)[KV_STRIDE] = (unsigned(*)[KV_STRIDE])(&Kn[warp * 16][0]);

    const float qscale = 0.125f * 1.4426950408889634f;  // 1/sqrt(D) * log2(e)

    // ---- Q fragments (register-resident for the whole block) ----
    unsigned qa[8][4];
    {
        const int r_lo = q0 + warp * 16 + lr;
        const float* Qlo = qkv + ((size_t)(b * TT + r_lo)) * N_QKV + h * DD;
        const float* Qhi = Qlo + (size_t)8 * N_QKV;
        #pragma unroll
        for (int kk8 = 0; kk8 < 8; kk8++) {
            int d0 = kk8 * 8 + lc;
            qa[kk8][0] = f2tf32(Qlo[d0]     * qscale);
            qa[kk8][1] = f2tf32(Qhi[d0]     * qscale);
            qa[kk8][2] = f2tf32(Qlo[d0 + 4] * qscale);
            qa[kk8][3] = f2tf32(Qhi[d0 + 4] * qscale);
        }
    }

    float O[8][4];
    #pragma unroll
    for (int nt = 0; nt < 8; nt++)
        #pragma unroll
        for (int r = 0; r < 4; r++) O[nt][r] = 0.0f;

    float m_lo = -1e30f, m_hi = -1e30f, l_lo = 0.0f, l_hi = 0.0f;
    const int qrl = warp * 16 + lr;          // local query row (lo)

    // Loader coordinates: 16 threads per row (16B each), 8 rows per pass
    const int ld_row = tid >> 4;             // 0..7
    const int ld_col = (tid & 15) * 4;       // 0..60

    for (int kt = 0; kt <= qb; kt++) {
        const int k0 = kt * 64;

        // ---- Load K/V tile (coalesced, tf32-converted) ----
        #pragma unroll
        for (int r = 0; r < 64; r += 8) {
            int key = r + ld_row;
            const float* kp = qkv + ((size_t)(b * TT + k0 + key)) * N_QKV + CC + h * DD + ld_col;
            float4 kv = *(const float4*)kp;
            float4 vv = *(const float4*)(kp + CC);
            uint4 kt4, vt4;
            kt4.x = f2tf32(kv.x); kt4.y = f2tf32(kv.y); kt4.z = f2tf32(kv.z); kt4.w = f2tf32(kv.w);
            vt4.x = f2tf32(vv.x); vt4.y = f2tf32(vv.y); vt4.z = f2tf32(vv.z); vt4.w = f2tf32(vv.w);
            *(uint4*)&Kn[key][ld_col] = kt4;
            *(uint4*)&Vs[key][ld_col] = vt4;
        }
        __syncthreads();

        // ---- S = Q K^T (16 x 64 per warp) ----
        float s[8][4];
        #pragma unroll
        for (int nt = 0; nt < 8; nt++)
            #pragma unroll
            for (int r = 0; r < 4; r++) s[nt][r] = 0.0f;

        #pragma unroll
        for (int kk8 = 0; kk8 < 8; kk8++) {
            const int dcol = kk8 * 8 + lc;
            #pragma unroll
            for (int nt = 0; nt < 8; nt++) {
                unsigned bfr[2];
                bfr[0] = Kn[nt * 8 + lr][dcol];       // element (d=dcol,   key=nt*8+lr)
                bfr[1] = Kn[nt * 8 + lr][dcol + 4];   // element (d=dcol+4, key)
                mma_tf32(s[nt], qa[kk8], bfr);
            }
        }

        // ---- Causal mask (diagonal tile only) ----
        if (kt == qb) {
            #pragma unroll
            for (int nt = 0; nt < 8; nt++) {
                int kcol = nt * 8 + 2 * lc;
                if (kcol     > qrl)     s[nt][0] = -1e30f;
                if (kcol + 1 > qrl)     s[nt][1] = -1e30f;
                if (kcol     > qrl + 8) s[nt][2] = -1e30f;
                if (kcol + 1 > qrl + 8) s[nt][3] = -1e30f;
            }
        }

        // ---- Online softmax (rows lr and lr+8; reduce over 4-lane group) ----
        float rl = -1e30f, rh = -1e30f;
        #pragma unroll
        for (int nt = 0; nt < 8; nt++) {
            rl = fmaxf(rl, fmaxf(s[nt][0], s[nt][1]));
            rh = fmaxf(rh, fmaxf(s[nt][2], s[nt][3]));
        }
        rl = fmaxf(rl, __shfl_xor_sync(0xffffffffu, rl, 1));
        rl = fmaxf(rl, __shfl_xor_sync(0xffffffffu, rl, 2));
        rh = fmaxf(rh, __shfl_xor_sync(0xffffffffu, rh, 1));
        rh = fmaxf(rh, __shfl_xor_sync(0xffffffffu, rh, 2));

        float mnl = fmaxf(m_lo, rl), mnh = fmaxf(m_hi, rh);
        float cl = exp2a(m_lo - mnl), ch = exp2a(m_hi - mnh);
        m_lo = mnl; m_hi = mnh;

        unsigned pb[8][4];
        float suml = 0.0f, sumh = 0.0f;
        #pragma unroll
        for (int nt = 0; nt < 8; nt++) {
            pb[nt][0] = f2tf32(exp2a(s[nt][0] - mnl));
            pb[nt][1] = f2tf32(exp2a(s[nt][1] - mnl));
            pb[nt][2] = f2tf32(exp2a(s[nt][2] - mnh));
            pb[nt][3] = f2tf32(exp2a(s[nt][3] - mnh));
            suml += __uint_as_float(pb[nt][0]) + __uint_as_float(pb[nt][1]);
            sumh += __uint_as_float(pb[nt][2]) + __uint_as_float(pb[nt][3]);
        }
        suml += __shfl_xor_sync(0xffffffffu, suml, 1);
        suml += __shfl_xor_sync(0xffffffffu, suml, 2);
        sumh += __shfl_xor_sync(0xffffffffu, sumh, 1);
        sumh += __shfl_xor_sync(0xffffffffu, sumh, 2);
        l_lo = l_lo * cl + suml;
        l_hi = l_hi * ch + sumh;

        #pragma unroll
        for (int nt = 0; nt < 8; nt++) {
            O[nt][0] *= cl; O[nt][1] *= cl;
            O[nt][2] *= ch; O[nt][3] *= ch;
        }

        // All warps done reading Kn -> safe to overwrite with P
        __syncthreads();

        #pragma unroll
        for (int nt = 0; nt < 8; nt++) {
            *(uint2*)&Ps[lr][nt * 8 + 2 * lc]     = make_uint2(pb[nt][0], pb[nt][1]);
            *(uint2*)&Ps[lr + 8][nt * 8 + 2 * lc] = make_uint2(pb[nt][2], pb[nt][3]);
        }
        __syncwarp();

        // ---- O += P V  (16 x 64 per warp) ----
        #pragma unroll
        for (int kk8 = 0; kk8 < 8; kk8++) {
            unsigned pa[4];
            pa[0] = Ps[lr][kk8 * 8 + lc];
            pa[1] = Ps[lr + 8][kk8 * 8 + lc];
            pa[2] = Ps[lr][kk8 * 8 + lc + 4];
            pa[3] = Ps[lr + 8][kk8 * 8 + lc + 4];
            #pragma unroll
            for (int nt = 0; nt < 8; nt++) {
                unsigned bfr[2];
                bfr[0] = Vs[kk8 * 8 + lc][nt * 8 + lr];        // element (key=kk8*8+lc,   d=nt*8+lr)
                bfr[1] = Vs[kk8 * 8 + lc + 4][nt * 8 + lr];    // element (key+4,          d)
                mma_tf32(O[nt], pa, bfr);
            }
        }
        __syncthreads();   // before next tile overwrites Kn/Vs (and Ps alias)
    }

    // ---- Epilogue: normalize and store ----
    const float il = 1.0f / l_lo;
    const float ih = 1.0f / l_hi;
    float* ylo = y + ((size_t)(b * TT + q0 + qrl)) * CC + h * DD;
    float* yhi = ylo + (size_t)8 * CC;
    #pragma unroll
    for (int nt = 0; nt < 8; nt++) {
        int c0 = nt * 8 + 2 * lc;
        *(float2*)&ylo[c0] = make_float2(O[nt][0] * il, O[nt][1] * il);
        *(float2*)&yhi[c0] = make_float2(O[nt][2] * ih, O[nt][3] * ih);
    }
}

// ---------------------------------------------------------------------------
// Launch
// ---------------------------------------------------------------------------
extern "C" void kernel_launch(void* const* d_in, const int* in_sizes, int n_in,
                              void* d_out, int out_size)
{
    const float* x      = (const float*)d_in[0];
    const float* w_qkv  = (const float*)d_in[1];
    const float* b_qkv  = (const float*)d_in[2];
    const float* w_proj = (const float*)d_in[3];
    const float* b_proj = (const float*)d_in[4];
    float* out = (float*)d_out;

    float* qkv = nullptr;
    float* y   = nullptr;
    cudaGetSymbolAddress((void**)&qkv, g_qkv);
    cudaGetSymbolAddress((void**)&y,   g_y);

    // 1) QKV projection: [8192,1024] @ [1024,3072] + bias
    {
        dim3 grid(N_QKV / TBN, M_ROWS / TBM);   // (24, 64)
        gemm_tf32_bias<<<grid, 256>>>(x, w_qkv, b_qkv, qkv, M_ROWS, N_QKV, CC);
    }

    // 2) Causal attention (tf32 mma flash)
    {
        dim3 grid(TT / 64, BB * HH);            // (32, 64)
        attn_mma<<<grid, 128>>>(qkv, y);
    }

    // 3) Output projection: [8192,1024] @ [1024,1024] + bias
    {
        dim3 grid(CC / TBN, M_ROWS / TBM);      // (8, 64)
        gemm_tf32_bias<<<grid, 256>>>(y, w_proj, b_proj, out, M_ROWS, CC, CC);
    }
}

// round 5
// speedup vs baseline: 3.8062x; 1.0096x over previous
#include <cuda_runtime.h>
#include <cuda_bf16.h>

// Problem constants
#define BB 4
#define TT 2048
#define CC 1024
#define HH 16
#define DD 64
#define M_ROWS (BB * TT)          // 8192
#define N_QKV  (3 * CC)           // 3072

// Scratch (device globals — allocation-free)
__device__ float g_qkv[(size_t)M_ROWS * N_QKV];   // [B*T, 3C]
__device__ float g_y[(size_t)M_ROWS * CC];        // [B*T, C]  (tf32-rounded by attention)
__device__ float g_xr[(size_t)M_ROWS * CC];       // x rounded to tf32
__device__ float g_wqkvr[(size_t)CC * N_QKV];     // w_qkv rounded
__device__ float g_wprojr[(size_t)CC * CC];       // w_proj rounded

__device__ __forceinline__ unsigned f2tf32(float x) {
    unsigned r;
    asm("cvt.rna.tf32.f32 %0, %1;" : "=r"(r) : "f"(x));
    return r;
}
__device__ __forceinline__ float rnd_tf32(float x) {
    return __uint_as_float(f2tf32(x));
}
__device__ __forceinline__ float exp2a(float x) {
    float r;
    asm("ex2.approx.ftz.f32 %0, %1;" : "=f"(r) : "f"(x));
    return r;
}
__device__ __forceinline__ void mma_tf32(float* c, const unsigned* a, const unsigned* b) {
    asm volatile(
        "mma.sync.aligned.m16n8k8.row.col.f32.tf32.tf32.f32 "
        "{%0,%1,%2,%3}, {%4,%5,%6,%7}, {%8,%9}, {%0,%1,%2,%3};"
        : "+f"(c[0]), "+f"(c[1]), "+f"(c[2]), "+f"(c[3])
        : "r"(a[0]), "r"(a[1]), "r"(a[2]), "r"(a[3]),
          "r"(b[0]), "r"(b[1]));
}

// ---------------------------------------------------------------------------
// Elementwise tf32 pre-round (float4-wide)
// ---------------------------------------------------------------------------
__global__ __launch_bounds__(256)
void round_tf32_kernel(const float* __restrict__ in, float* __restrict__ out, int n4)
{
    int i = blockIdx.x * blockDim.x + threadIdx.x;
    if (i >= n4) return;
    float4 v = ((const float4*)in)[i];
    v.x = rnd_tf32(v.x); v.y = rnd_tf32(v.y);
    v.z = rnd_tf32(v.z); v.w = rnd_tf32(v.w);
    ((float4*)out)[i] = v;
}

// ---------------------------------------------------------------------------
// TF32 GEMM v2: pre-rounded inputs, permuted smem for LDS.128 fragment loads,
// double-buffered.  C[M,N] = A[M,K] @ B[K,N] + bias[N]
// 128x128x16 block, 8 warps, 64x32 warp tile.
//
// A smem word(row,k)  = row*16 + 4*((k&3)^s(row)) + (k>>2),  s=(row^(row>>2))&3
//   -> one LDS.128 at row*16+4*(lc^s) yields a-regs for k8=0 and k8=1.
// B smem word(k,n)    = k*132 + (n&7)*16 + (n>>3)
//   -> one LDS.128 at k*132+lr*16+wn8 yields bf[nt=0..3].
// ---------------------------------------------------------------------------
#define TBM 128
#define TBN 128
#define TBK 16

__global__ __launch_bounds__(256, 2)
void gemm_tf32_v2(const float* __restrict__ A,
                  const float* __restrict__ B,
                  const float* __restrict__ bias,
                  float* __restrict__ C,
                  int M, int N, int K)
{
    __shared__ unsigned As[2][TBM * 16];     // 16 KB
    __shared__ unsigned Bs[2][TBK * 132];    // 16.5 KB

    const int tid  = threadIdx.x;
    const int warp = tid >> 5;
    const int lane = tid & 31;
    const int lr = lane >> 2;
    const int lc = lane & 3;
    const int wm = (warp >> 2) * 64;
    const int wn = (warp & 3) * 32;
    const int wn8 = wn >> 3;

    const int blockM = blockIdx.y * TBM;
    const int blockN = blockIdx.x * TBN;

    // Global-load coordinates
    const int a0r = tid >> 2, ac = (tid & 3) * 4;   // A rows 0..63 / 64..127
    const int a1r = a0r + 64;
    const int b0r = tid >> 5, bc = (tid & 31) * 4;  // B k-rows 0..7 / 8..15
    const int b1r = b0r + 8;

    const float* Ag = A + (size_t)blockM * K;
    const float* Bg = B + blockN;

    // STS word bases
    const int sA0 = (a0r ^ (a0r >> 2)) & 3;
    const int sA1 = (a1r ^ (a1r >> 2)) & 3;
    const int aw0 = a0r * 16 + (ac >> 2);
    const int aw1 = a1r * 16 + (ac >> 2);
    const int bw0 = b0r * 132 + (bc & 7) * 16 + (bc >> 3);
    const int bw1 = b1r * 132 + (bc & 7) * 16 + (bc >> 3);

    // A fragment LDS bases (per mt: rows rm, rm+8)
    int aRd[4][2];
    #pragma unroll
    for (int mt = 0; mt < 4; mt++) {
        int rm = wm + mt * 16 + lr;
        int r8 = rm + 8;
        aRd[mt][0] = rm * 16 + 4 * (lc ^ ((rm ^ (rm >> 2)) & 3));
        aRd[mt][1] = r8 * 16 + 4 * (lc ^ ((r8 ^ (r8 >> 2)) & 3));
    }
    // B fragment LDS bases: kk8 in {0,1}, k-half in {0,+4}
    const int bRd = lr * 16 + wn8;

    float acc[4][4][4];
    #pragma unroll
    for (int i = 0; i < 4; i++)
        #pragma unroll
        for (int j = 0; j < 4; j++)
            #pragma unroll
            for (int r = 0; r < 4; r++) acc[i][j][r] = 0.0f;

    float4 ra0, ra1, rb0, rb1;

    // Prologue: tile 0 -> regs -> smem buf 0
    ra0 = *(const float4*)&Ag[(size_t)a0r * K + ac];
    ra1 = *(const float4*)&Ag[(size_t)a1r * K + ac];
    rb0 = *(const float4*)&Bg[(size_t)b0r * N + bc];
    rb1 = *(const float4*)&Bg[(size_t)b1r * N + bc];

    As[0][aw0 + 4 * (0 ^ sA0)] = __float_as_uint(ra0.x);
    As[0][aw0 + 4 * (1 ^ sA0)] = __float_as_uint(ra0.y);
    As[0][aw0 + 4 * (2 ^ sA0)] = __float_as_uint(ra0.z);
    As[0][aw0 + 4 * (3 ^ sA0)] = __float_as_uint(ra0.w);
    As[0][aw1 + 4 * (0 ^ sA1)] = __float_as_uint(ra1.x);
    As[0][aw1 + 4 * (1 ^ sA1)] = __float_as_uint(ra1.y);
    As[0][aw1 + 4 * (2 ^ sA1)] = __float_as_uint(ra1.z);
    As[0][aw1 + 4 * (3 ^ sA1)] = __float_as_uint(ra1.w);
    Bs[0][bw0]      = __float_as_uint(rb0.x);
    Bs[0][bw0 + 16] = __float_as_uint(rb0.y);
    Bs[0][bw0 + 32] = __float_as_uint(rb0.z);
    Bs[0][bw0 + 48] = __float_as_uint(rb0.w);
    Bs[0][bw1]      = __float_as_uint(rb1.x);
    Bs[0][bw1 + 16] = __float_as_uint(rb1.y);
    Bs[0][bw1 + 32] = __float_as_uint(rb1.z);
    Bs[0][bw1 + 48] = __float_as_uint(rb1.w);
    __syncthreads();

    int buf = 0;
    for (int k0 = 0; k0 < K; k0 += TBK) {
        const bool more = (k0 + TBK) < K;
        if (more) {
            const int kn = k0 + TBK;
            ra0 = *(const float4*)&Ag[(size_t)a0r * K + kn + ac];
            ra1 = *(const float4*)&Ag[(size_t)a1r * K + kn + ac];
            rb0 = *(const float4*)&Bg[(size_t)(kn + b0r) * N + bc];
            rb1 = *(const float4*)&Bg[(size_t)(kn + b1r) * N + bc];
        }

        // B fragments for both k8 steps (4 x LDS.128)
        const unsigned* bsb = &Bs[buf][0];
        uint4 b00 = *(const uint4*)&bsb[(lc)     * 132 + bRd];   // k8=0, k-lo
        uint4 b01 = *(const uint4*)&bsb[(lc + 4) * 132 + bRd];   // k8=0, k-hi
        uint4 b10 = *(const uint4*)&bsb[(lc + 8) * 132 + bRd];   // k8=1, k-lo
        uint4 b11 = *(const uint4*)&bsb[(lc + 12)* 132 + bRd];   // k8=1, k-hi

        const unsigned* asb = &As[buf][0];
        #pragma unroll
        for (int mt = 0; mt < 4; mt++) {
            uint4 lo = *(const uint4*)&asb[aRd[mt][0]];
            uint4 hi = *(const uint4*)&asb[aRd[mt][1]];
            // k8=0 fragment: {a0,a1,a2,a3} = {lo.x, hi.x, lo.y, hi.y}
            unsigned af0[4] = { lo.x, hi.x, lo.y, hi.y };
            unsigned af1[4] = { lo.z, hi.z, lo.w, hi.w };
            {
                unsigned bf[2];
                bf[0] = b00.x; bf[1] = b01.x; mma_tf32(acc[mt][0], af0, bf);
                bf[0] = b00.y; bf[1] = b01.y; mma_tf32(acc[mt][1], af0, bf);
                bf[0] = b00.z; bf[1] = b01.z; mma_tf32(acc[mt][2], af0, bf);
                bf[0] = b00.w; bf[1] = b01.w; mma_tf32(acc[mt][3], af0, bf);
                bf[0] = b10.x; bf[1] = b11.x; mma_tf32(acc[mt][0], af1, bf);
                bf[0] = b10.y; bf[1] = b11.y; mma_tf32(acc[mt][1], af1, bf);
                bf[0] = b10.z; bf[1] = b11.z; mma_tf32(acc[mt][2], af1, bf);
                bf[0] = b10.w; bf[1] = b11.w; mma_tf32(acc[mt][3], af1, bf);
            }
        }

        if (more) {
            const int d = buf ^ 1;
            As[d][aw0 + 4 * (0 ^ sA0)] = __float_as_uint(ra0.x);
            As[d][aw0 + 4 * (1 ^ sA0)] = __float_as_uint(ra0.y);
            As[d][aw0 + 4 * (2 ^ sA0)] = __float_as_uint(ra0.z);
            As[d][aw0 + 4 * (3 ^ sA0)] = __float_as_uint(ra0.w);
            As[d][aw1 + 4 * (0 ^ sA1)] = __float_as_uint(ra1.x);
            As[d][aw1 + 4 * (1 ^ sA1)] = __float_as_uint(ra1.y);
            As[d][aw1 + 4 * (2 ^ sA1)] = __float_as_uint(ra1.z);
            As[d][aw1 + 4 * (3 ^ sA1)] = __float_as_uint(ra1.w);
            Bs[d][bw0]      = __float_as_uint(rb0.x);
            Bs[d][bw0 + 16] = __float_as_uint(rb0.y);
            Bs[d][bw0 + 32] = __float_as_uint(rb0.z);
            Bs[d][bw0 + 48] = __float_as_uint(rb0.w);
            Bs[d][bw1]      = __float_as_uint(rb1.x);
            Bs[d][bw1 + 16] = __float_as_uint(rb1.y);
            Bs[d][bw1 + 32] = __float_as_uint(rb1.z);
            Bs[d][bw1 + 48] = __float_as_uint(rb1.w);
        }
        __syncthreads();
        buf ^= 1;
    }

    // Epilogue: bias add + store
    #pragma unroll
    for (int mt = 0; mt < 4; mt++) {
        #pragma unroll
        for (int nt = 0; nt < 4; nt++) {
            int r0 = blockM + wm + mt * 16 + lr;
            int c0 = blockN + wn + nt * 8 + lc * 2;
            float bx = bias[c0], by = bias[c0 + 1];
            float2 v0 = make_float2(acc[mt][nt][0] + bx, acc[mt][nt][1] + by);
            float2 v1 = make_float2(acc[mt][nt][2] + bx, acc[mt][nt][3] + by);
            *(float2*)&C[(size_t)r0 * N + c0]       = v0;
            *(float2*)&C[(size_t)(r0 + 8) * N + c0] = v1;
        }
    }
}

// ---------------------------------------------------------------------------
// TF32 MMA causal flash attention (verified R4). Epilogue now rounds y to tf32
// so the output projection can skip conversion.
// ---------------------------------------------------------------------------
#define KV_STRIDE 68

__global__ __launch_bounds__(128, 2)
void attn_mma(const float* __restrict__ qkv, float* __restrict__ y)
{
    __shared__ unsigned Kn[64][KV_STRIDE];
    __shared__ unsigned Vs[64][KV_STRIDE];

    const int tid  = threadIdx.x;
    const int warp = tid >> 5;
    const int lane = tid & 31;
    const int lr = lane >> 2;
    const int lc = lane & 3;

    const int qb = blockIdx.x;
    const int bh = blockIdx.y;
    const int b  = bh >> 4;
    const int h  = bh & 15;
    const int q0 = qb * 64;

    unsigned (*Ps)[KV_STRIDE] = (unsigned(*)[KV_STRIDE])(&Kn[warp * 16][0]);

    const float qscale = 0.125f * 1.4426950408889634f;

    unsigned qa[8][4];
    {
        const int r_lo = q0 + warp * 16 + lr;
        const float* Qlo = qkv + ((size_t)(b * TT + r_lo)) * N_QKV + h * DD;
        const float* Qhi = Qlo + (size_t)8 * N_QKV;
        #pragma unroll
        for (int kk8 = 0; kk8 < 8; kk8++) {
            int d0 = kk8 * 8 + lc;
            qa[kk8][0] = f2tf32(Qlo[d0]     * qscale);
            qa[kk8][1] = f2tf32(Qhi[d0]     * qscale);
            qa[kk8][2] = f2tf32(Qlo[d0 + 4] * qscale);
            qa[kk8][3] = f2tf32(Qhi[d0 + 4] * qscale);
        }
    }

    float O[8][4];
    #pragma unroll
    for (int nt = 0; nt < 8; nt++)
        #pragma unroll
        for (int r = 0; r < 4; r++) O[nt][r] = 0.0f;

    float m_lo = -1e30f, m_hi = -1e30f, l_lo = 0.0f, l_hi = 0.0f;
    const int qrl = warp * 16 + lr;

    const int ld_row = tid >> 4;
    const int ld_col = (tid & 15) * 4;

    for (int kt = 0; kt <= qb; kt++) {
        const int k0 = kt * 64;

        #pragma unroll
        for (int r = 0; r < 64; r += 8) {
            int key = r + ld_row;
            const float* kp = qkv + ((size_t)(b * TT + k0 + key)) * N_QKV + CC + h * DD + ld_col;
            float4 kv = *(const float4*)kp;
            float4 vv = *(const float4*)(kp + CC);
            uint4 kt4, vt4;
            kt4.x = f2tf32(kv.x); kt4.y = f2tf32(kv.y); kt4.z = f2tf32(kv.z); kt4.w = f2tf32(kv.w);
            vt4.x = f2tf32(vv.x); vt4.y = f2tf32(vv.y); vt4.z = f2tf32(vv.z); vt4.w = f2tf32(vv.w);
            *(uint4*)&Kn[key][ld_col] = kt4;
            *(uint4*)&Vs[key][ld_col] = vt4;
        }
        __syncthreads();

        float s[8][4];
        #pragma unroll
        for (int nt = 0; nt < 8; nt++)
            #pragma unroll
            for (int r = 0; r < 4; r++) s[nt][r] = 0.0f;

        #pragma unroll
        for (int kk8 = 0; kk8 < 8; kk8++) {
            const int dcol = kk8 * 8 + lc;
            #pragma unroll
            for (int nt = 0; nt < 8; nt++) {
                unsigned bfr[2];
                bfr[0] = Kn[nt * 8 + lr][dcol];
                bfr[1] = Kn[nt * 8 + lr][dcol + 4];
                mma_tf32(s[nt], qa[kk8], bfr);
            }
        }

        if (kt == qb) {
            #pragma unroll
            for (int nt = 0; nt < 8; nt++) {
                int kcol = nt * 8 + 2 * lc;
                if (kcol     > qrl)     s[nt][0] = -1e30f;
                if (kcol + 1 > qrl)     s[nt][1] = -1e30f;
                if (kcol     > qrl + 8) s[nt][2] = -1e30f;
                if (kcol + 1 > qrl + 8) s[nt][3] = -1e30f;
            }
        }

        float rl = -1e30f, rh = -1e30f;
        #pragma unroll
        for (int nt = 0; nt < 8; nt++) {
            rl = fmaxf(rl, fmaxf(s[nt][0], s[nt][1]));
            rh = fmaxf(rh, fmaxf(s[nt][2], s[nt][3]));
        }
        rl = fmaxf(rl, __shfl_xor_sync(0xffffffffu, rl, 1));
        rl = fmaxf(rl, __shfl_xor_sync(0xffffffffu, rl, 2));
        rh = fmaxf(rh, __shfl_xor_sync(0xffffffffu, rh, 1));
        rh = fmaxf(rh, __shfl_xor_sync(0xffffffffu, rh, 2));

        float mnl = fmaxf(m_lo, rl), mnh = fmaxf(m_hi, rh);
        float cl = exp2a(m_lo - mnl), ch = exp2a(m_hi - mnh);
        m_lo = mnl; m_hi = mnh;

        unsigned pb[8][4];
        float suml = 0.0f, sumh = 0.0f;
        #pragma unroll
        for (int nt = 0; nt < 8; nt++) {
            pb[nt][0] = f2tf32(exp2a(s[nt][0] - mnl));
            pb[nt][1] = f2tf32(exp2a(s[nt][1] - mnl));
            pb[nt][2] = f2tf32(exp2a(s[nt][2] - mnh));
            pb[nt][3] = f2tf32(exp2a(s[nt][3] - mnh));
            suml += __uint_as_float(pb[nt][0]) + __uint_as_float(pb[nt][1]);
            sumh += __uint_as_float(pb[nt][2]) + __uint_as_float(pb[nt][3]);
        }
        suml += __shfl_xor_sync(0xffffffffu, suml, 1);
        suml += __shfl_xor_sync(0xffffffffu, suml, 2);
        sumh += __shfl_xor_sync(0xffffffffu, sumh, 1);
        sumh += __shfl_xor_sync(0xffffffffu, sumh, 2);
        l_lo = l_lo * cl + suml;
        l_hi = l_hi * ch + sumh;

        #pragma unroll
        for (int nt = 0; nt < 8; nt++) {
            O[nt][0] *= cl; O[nt][1] *= cl;
            O[nt][2] *= ch; O[nt][3] *= ch;
        }

        __syncthreads();

        #pragma unroll
        for (int nt = 0; nt < 8; nt++) {
            *(uint2*)&Ps[lr][nt * 8 + 2 * lc]     = make_uint2(pb[nt][0], pb[nt][1]);
            *(uint2*)&Ps[lr + 8][nt * 8 + 2 * lc] = make_uint2(pb[nt][2], pb[nt][3]);
        }
        __syncwarp();

        #pragma unroll
        for (int kk8 = 0; kk8 < 8; kk8++) {
            unsigned pa[4];
            pa[0] = Ps[lr][kk8 * 8 + lc];
            pa[1] = Ps[lr + 8][kk8 * 8 + lc];
            pa[2] = Ps[lr][kk8 * 8 + lc + 4];
            pa[3] = Ps[lr + 8][kk8 * 8 + lc + 4];
            #pragma unroll
            for (int nt = 0; nt < 8; nt++) {
                unsigned bfr[2];
                bfr[0] = Vs[kk8 * 8 + lc][nt * 8 + lr];
                bfr[1] = Vs[kk8 * 8 + lc + 4][nt * 8 + lr];
                mma_tf32(O[nt], pa, bfr);
            }
        }
        __syncthreads();
    }

    const float il = 1.0f / l_lo;
    const float ih = 1.0f / l_hi;
    float* ylo = y + ((size_t)(b * TT + q0 + qrl)) * CC + h * DD;
    float* yhi = ylo + (size_t)8 * CC;
    #pragma unroll
    for (int nt = 0; nt < 8; nt++) {
        int c0 = nt * 8 + 2 * lc;
        *(float2*)&ylo[c0] = make_float2(rnd_tf32(O[nt][0] * il), rnd_tf32(O[nt][1] * il));
        *(float2*)&yhi[c0] = make_float2(rnd_tf32(O[nt][2] * ih), rnd_tf32(O[nt][3] * ih));
    }
}

// ---------------------------------------------------------------------------
// Launch
// ---------------------------------------------------------------------------
extern "C" void kernel_launch(void* const* d_in, const int* in_sizes, int n_in,
                              void* d_out, int out_size)
{
    const float* x      = (const float*)d_in[0];
    const float* w_qkv  = (const float*)d_in[1];
    const float* b_qkv  = (const float*)d_in[2];
    const float* w_proj = (const float*)d_in[3];
    const float* b_proj = (const float*)d_in[4];
    float* out = (float*)d_out;

    float *qkv, *y, *xr, *wqkvr, *wprojr;
    cudaGetSymbolAddress((void**)&qkv,    g_qkv);
    cudaGetSymbolAddress((void**)&y,      g_y);
    cudaGetSymbolAddress((void**)&xr,     g_xr);
    cudaGetSymbolAddress((void**)&wqkvr,  g_wqkvr);
    cudaGetSymbolAddress((void**)&wprojr, g_wprojr);

    // 0) Pre-round inputs to tf32
    {
        int n4x = (M_ROWS * CC) / 4;
        round_tf32_kernel<<<(n4x + 255) / 256, 256>>>(x, xr, n4x);
        int n4w = (CC * N_QKV) / 4;
        round_tf32_kernel<<<(n4w + 255) / 256, 256>>>(w_qkv, wqkvr, n4w);
        int n4p = (CC * CC) / 4;
        round_tf32_kernel<<<(n4p + 255) / 256, 256>>>(w_proj, wprojr, n4p);
    }

    // 1) QKV projection
    {
        dim3 grid(N_QKV / TBN, M_ROWS / TBM);   // (24, 64)
        gemm_tf32_v2<<<grid, 256>>>(xr, wqkvr, b_qkv, qkv, M_ROWS, N_QKV, CC);
    }

    // 2) Causal attention
    {
        dim3 grid(TT / 64, BB * HH);            // (32, 64)
        attn_mma<<<grid, 128>>>(qkv, y);
    }

    // 3) Output projection
    {
        dim3 grid(CC / TBN, M_ROWS / TBM);      // (8, 64)
        gemm_tf32_v2<<<grid, 256>>>(y, wprojr, b_proj, out, M_ROWS, CC, CC);
    }
}

// round 7
// speedup vs baseline: 3.8898x; 1.0219x over previous
#include <cuda_runtime.h>
#include <cuda_bf16.h>
#include <cstdint>

// Problem constants
#define BB 4
#define TT 2048
#define CC 1024
#define HH 16
#define DD 64
#define M_ROWS (BB * TT)          // 8192
#define N_QKV  (3 * CC)           // 3072

// Scratch (device globals — allocation-free)
__device__ float g_qkv[(size_t)M_ROWS * N_QKV];       // [B*T, 3C] (tf32-rounded)
__device__ float g_y[(size_t)M_ROWS * CC];            // attention output
__device__ float g_xp[(size_t)M_ROWS * CC];           // x, permuted A-tiles
__device__ float g_yp[(size_t)M_ROWS * CC];           // y, permuted A-tiles
__device__ float g_wqkvp[(size_t)CC * N_QKV];         // w_qkv, permuted B-tiles
__device__ float g_wprojp[(size_t)CC * CC];           // w_proj, permuted B-tiles

// ---------------------------------------------------------------------------
// Helpers
// ---------------------------------------------------------------------------
__device__ __forceinline__ unsigned f2tf32(float x) {
    unsigned r;
    asm("cvt.rna.tf32.f32 %0, %1;" : "=r"(r) : "f"(x));
    return r;
}
__device__ __forceinline__ float rnd_tf32(float x) {
    return __uint_as_float(f2tf32(x));
}
__device__ __forceinline__ float exp2a(float x) {
    float r;
    asm("ex2.approx.ftz.f32 %0, %1;" : "=f"(r) : "f"(x));
    return r;
}
__device__ __forceinline__ void mma_tf32(float* c, const unsigned* a, const unsigned* b) {
    asm volatile(
        "mma.sync.aligned.m16n8k8.row.col.f32.tf32.tf32.f32 "
        "{%0,%1,%2,%3}, {%4,%5,%6,%7}, {%8,%9}, {%0,%1,%2,%3};"
        : "+f"(c[0]), "+f"(c[1]), "+f"(c[2]), "+f"(c[3])
        : "r"(a[0]), "r"(a[1]), "r"(a[2]), "r"(a[3]),
          "r"(b[0]), "r"(b[1]));
}
__device__ __forceinline__ uint32_t smem_u32(const void* p) {
    uint32_t a;
    asm("{ .reg .u64 t; cvta.to.shared.u64 t, %1; cvt.u32.u64 %0, t; }" : "=r"(a) : "l"(p));
    return a;
}
__device__ __forceinline__ void cp16(uint32_t s, const void* g) {
    asm volatile("cp.async.cg.shared.global [%0], [%1], 16;" :: "r"(s), "l"(g));
}
__device__ __forceinline__ void cp_commit() {
    asm volatile("cp.async.commit_group;" ::: "memory");
}

// ---------------------------------------------------------------------------
// Prep: permute A (row-major [M][K] fp32) into GEMM A-tile layout, tf32-rounded.
// Tile (mb, kb) word w: row=w>>4, rem=w&15, q=rem>>2, t=rem&3,
//   s=(row^(row>>2))&3, k=(t<<2)|(q^s)  -> value in[(mb*128+row)*K + kb*16+k]
// ---------------------------------------------------------------------------
__global__ __launch_bounds__(256)
void permute_a_kernel(const float* __restrict__ in, float* __restrict__ out, int K, int nTot)
{
    int idx = blockIdx.x * 256 + threadIdx.x;
    if (idx >= nTot) return;
    const int nk = K >> 4;
    int tile = idx >> 11, w = idx & 2047;
    int mb = tile / nk, kb = tile - mb * nk;
    int row = w >> 4, rem = w & 15;
    int q = rem >> 2, t = rem & 3;
    int s = (row ^ (row >> 2)) & 3;
    int k = (t << 2) | (q ^ s);
    out[idx] = rnd_tf32(in[(size_t)(mb * 128 + row) * K + kb * 16 + k]);
}

// ---------------------------------------------------------------------------
// Prep: permute B (row-major [K][N] fp32) into GEMM B-tile layout, tf32-rounded.
// Tile (nb, kb) word w: k=w>>7, p=w&127, n=(p&15)*8+(p>>4)
//   -> value in[(kb*16+k)*N + nb*128+n]
// ---------------------------------------------------------------------------
__global__ __launch_bounds__(256)
void permute_b_kernel(const float* __restrict__ in, float* __restrict__ out, int N, int K, int nTot)
{
    int idx = blockIdx.x * 256 + threadIdx.x;
    if (idx >= nTot) return;
    const int nk = K >> 4;
    int tile = idx >> 11, w = idx & 2047;
    int nb = tile / nk, kb = tile - nb * nk;
    int k = w >> 7, p = w & 127;
    int n = (p & 15) * 8 + (p >> 4);
    out[idx] = rnd_tf32(in[(size_t)(kb * 16 + k) * N + nb * 128 + n]);
}

// ---------------------------------------------------------------------------
// Pipelined TF32 mma.sync GEMM:  C[M,N] = A @ B + bias.
// A/B pre-permuted tile layouts; 4-stage cp.async; 128x128x16 block; 8 warps.
// smem: A stages [4][2048 words] at 0; B stages [4][2112 words] at 32768B.
// ---------------------------------------------------------------------------
#define GSM_BYTES 66560

__device__ __forceinline__ void gemm_load_stage(uint32_t sb, const float* Atile,
                                                const float* Btile, int s, int kb, int tid)
{
    const float* Ab = Atile + (size_t)kb * 2048;
    const float* Bb = Btile + (size_t)kb * 2048;
    const uint32_t as_ = sb + s * 8192;
    const uint32_t bs_ = sb + 32768 + s * 8448;
    cp16(as_ + tid * 16, Ab + tid * 4);
    cp16(as_ + (tid + 256) * 16, Ab + (tid + 256) * 4);
    const int c0 = tid, c1 = tid + 256;
    cp16(bs_ + (c0 >> 5) * 528 + (c0 & 31) * 16, Bb + c0 * 4);
    cp16(bs_ + (c1 >> 5) * 528 + (c1 & 31) * 16, Bb + c1 * 4);
    cp_commit();
}

template <bool ROUND>
__global__ __launch_bounds__(256, 2)
void gemm_pipe(const float* __restrict__ Ap, const float* __restrict__ Bp,
               const float* __restrict__ bias, float* __restrict__ C,
               int N, int K)
{
    extern __shared__ char smem[];
    const uint32_t sb = smem_u32(smem);
    const int tid  = threadIdx.x;
    const int warp = tid >> 5;
    const int lane = tid & 31;
    const int lr = lane >> 2;
    const int lc = lane & 3;
    const int wm = (warp >> 2) * 64;
    const int wn = (warp & 3) * 32;
    const int wn8 = wn >> 3;
    const int nk = K >> 4;

    const float* Atile = Ap + (size_t)blockIdx.y * nk * 2048;
    const float* Btile = Bp + (size_t)blockIdx.x * nk * 2048;

    // Fragment LDS word offsets (verified R5 layout)
    int aRd[4][2];
    #pragma unroll
    for (int mt = 0; mt < 4; mt++) {
        int rm = wm + mt * 16 + lr;
        int r8 = rm + 8;
        aRd[mt][0] = rm * 16 + 4 * (lc ^ ((rm ^ (rm >> 2)) & 3));
        aRd[mt][1] = r8 * 16 + 4 * (lc ^ ((r8 ^ (r8 >> 2)) & 3));
    }
    const int bRd = lr * 16 + wn8;

    float acc[4][4][4];
    #pragma unroll
    for (int i = 0; i < 4; i++)
        #pragma unroll
        for (int j = 0; j < 4; j++)
            #pragma unroll
            for (int r = 0; r < 4; r++) acc[i][j][r] = 0.0f;

    // Prologue: stages 0..2
    gemm_load_stage(sb, Atile, Btile, 0, 0, tid);
    gemm_load_stage(sb, Atile, Btile, 1, 1, tid);
    gemm_load_stage(sb, Atile, Btile, 2, 2, tid);

    for (int i = 0; i < nk; i++) {
        if (i + 3 <= nk)
            asm volatile("cp.async.wait_group 2;" ::: "memory");
        else
            asm volatile("cp.async.wait_group 0;" ::: "memory");
        __syncthreads();

        if (i + 3 < nk)
            gemm_load_stage(sb, Atile, Btile, (i + 3) & 3, i + 3, tid);

        const unsigned* asb = (const unsigned*)(smem + (size_t)(i & 3) * 8192);
        const unsigned* bsb = (const unsigned*)(smem + 32768 + (size_t)(i & 3) * 8448);

        uint4 b00 = *(const uint4*)&bsb[(lc)      * 132 + bRd];
        uint4 b01 = *(const uint4*)&bsb[(lc + 4)  * 132 + bRd];
        uint4 b10 = *(const uint4*)&bsb[(lc + 8)  * 132 + bRd];
        uint4 b11 = *(const uint4*)&bsb[(lc + 12) * 132 + bRd];

        #pragma unroll
        for (int mt = 0; mt < 4; mt++) {
            uint4 lo = *(const uint4*)&asb[aRd[mt][0]];
            uint4 hi = *(const uint4*)&asb[aRd[mt][1]];
            unsigned af0[4] = { lo.x, hi.x, lo.y, hi.y };
            unsigned af1[4] = { lo.z, hi.z, lo.w, hi.w };
            unsigned bf[2];
            bf[0] = b00.x; bf[1] = b01.x; mma_tf32(acc[mt][0], af0, bf);
            bf[0] = b00.y; bf[1] = b01.y; mma_tf32(acc[mt][1], af0, bf);
            bf[0] = b00.z; bf[1] = b01.z; mma_tf32(acc[mt][2], af0, bf);
            bf[0] = b00.w; bf[1] = b01.w; mma_tf32(acc[mt][3], af0, bf);
            bf[0] = b10.x; bf[1] = b11.x; mma_tf32(acc[mt][0], af1, bf);
            bf[0] = b10.y; bf[1] = b11.y; mma_tf32(acc[mt][1], af1, bf);
            bf[0] = b10.z; bf[1] = b11.z; mma_tf32(acc[mt][2], af1, bf);
            bf[0] = b10.w; bf[1] = b11.w; mma_tf32(acc[mt][3], af1, bf);
        }
    }

    // Epilogue: bias add (+ optional tf32 rounding) + store
    const int blockM = blockIdx.y * 128;
    const int blockN = blockIdx.x * 128;
    #pragma unroll
    for (int mt = 0; mt < 4; mt++) {
        #pragma unroll
        for (int nt = 0; nt < 4; nt++) {
            int r0 = blockM + wm + mt * 16 + lr;
            int c0 = blockN + wn + nt * 8 + lc * 2;
            float bx = bias[c0], by = bias[c0 + 1];
            float v0x = acc[mt][nt][0] + bx, v0y = acc[mt][nt][1] + by;
            float v1x = acc[mt][nt][2] + bx, v1y = acc[mt][nt][3] + by;
            if (ROUND) {
                v0x = rnd_tf32(v0x); v0y = rnd_tf32(v0y);
                v1x = rnd_tf32(v1x); v1y = rnd_tf32(v1y);
            }
            *(float2*)&C[(size_t)r0 * N + c0]       = make_float2(v0x, v0y);
            *(float2*)&C[(size_t)(r0 + 8) * N + c0] = make_float2(v1x, v1y);
        }
    }
}

// ---------------------------------------------------------------------------
// TF32 MMA causal flash attention, double-buffered cp.async K/V.
// qkv is already tf32-rounded (GEMM1 epilogue), so raw copies are exact.
// Dynamic smem: K0,V0,K1,V1 each 64x68 words (17408 B) -> 69632 B total.
// ---------------------------------------------------------------------------
#define ASM_BYTES 69632

__device__ __forceinline__ void attn_load_kv(uint32_t sb, const float* qkv,
                                             size_t bT, int k0, int h, int buf, int tid)
{
    const uint32_t kbase = sb + buf * 34816;
    #pragma unroll
    for (int i = 0; i < 8; i++) {
        int c = tid + i * 128;
        int key = c >> 4;
        int cw  = c & 15;
        const float* g = qkv + (bT + k0 + key) * N_QKV + CC + h * DD + cw * 4;
        uint32_t d = kbase + key * 272 + cw * 16;
        cp16(d, g);                       // K
        cp16(d + 17408, g + CC);          // V
    }
    cp_commit();
}

__global__ __launch_bounds__(128)
void attn_mma(const float* __restrict__ qkv, float* __restrict__ y)
{
    extern __shared__ unsigned kvmem[];
    const uint32_t sb = smem_u32(kvmem);

    const int tid  = threadIdx.x;
    const int warp = tid >> 5;
    const int lane = tid & 31;
    const int lr = lane >> 2;
    const int lc = lane & 3;

    const int qb = blockIdx.x;
    const int bh = blockIdx.y;
    const int b  = bh >> 4;
    const int h  = bh & 15;
    const int q0 = qb * 64;
    const size_t bT = (size_t)b * TT;

    const float qscale = 0.125f * 1.4426950408889634f;

    // Q fragments (register-resident)
    unsigned qa[8][4];
    {
        const int r_lo = q0 + warp * 16 + lr;
        const float* Qlo = qkv + (bT + r_lo) * N_QKV + h * DD;
        const float* Qhi = Qlo + (size_t)8 * N_QKV;
        #pragma unroll
        for (int kk8 = 0; kk8 < 8; kk8++) {
            int d0 = kk8 * 8 + lc;
            qa[kk8][0] = f2tf32(Qlo[d0]     * qscale);
            qa[kk8][1] = f2tf32(Qhi[d0]     * qscale);
            qa[kk8][2] = f2tf32(Qlo[d0 + 4] * qscale);
            qa[kk8][3] = f2tf32(Qhi[d0 + 4] * qscale);
        }
    }

    float O[8][4];
    #pragma unroll
    for (int nt = 0; nt < 8; nt++)
        #pragma unroll
        for (int r = 0; r < 4; r++) O[nt][r] = 0.0f;

    float m_lo = -1e30f, m_hi = -1e30f, l_lo = 0.0f, l_hi = 0.0f;
    const int qrl = warp * 16 + lr;

    // Prologue: tile 0 into buffer 0
    attn_load_kv(sb, qkv, bT, 0, h, 0, tid);

    for (int kt = 0; kt <= qb; kt++) {
        const int buf = kt & 1;
        if (kt < qb) {
            attn_load_kv(sb, qkv, bT, (kt + 1) * 64, h, buf ^ 1, tid);
            asm volatile("cp.async.wait_group 1;" ::: "memory");
        } else {
            asm volatile("cp.async.wait_group 0;" ::: "memory");
        }
        __syncthreads();

        unsigned* Kn  = kvmem + buf * 8704;
        unsigned* Vsp = Kn + 4352;
        unsigned* Psp = Kn + warp * 16 * 68;

        // ---- S = Q K^T ----
        float s[8][4];
        #pragma unroll
        for (int nt = 0; nt < 8; nt++)
            #pragma unroll
            for (int r = 0; r < 4; r++) s[nt][r] = 0.0f;

        #pragma unroll
        for (int kk8 = 0; kk8 < 8; kk8++) {
            const int dcol = kk8 * 8 + lc;
            #pragma unroll
            for (int nt = 0; nt < 8; nt++) {
                unsigned bfr[2];
                bfr[0] = Kn[(nt * 8 + lr) * 68 + dcol];
                bfr[1] = Kn[(nt * 8 + lr) * 68 + dcol + 4];
                mma_tf32(s[nt], qa[kk8], bfr);
            }
        }

        // ---- Causal mask (diagonal tile) ----
        if (kt == qb) {
            #pragma unroll
            for (int nt = 0; nt < 8; nt++) {
                int kcol = nt * 8 + 2 * lc;
                if (kcol     > qrl)     s[nt][0] = -1e30f;
                if (kcol + 1 > qrl)     s[nt][1] = -1e30f;
                if (kcol     > qrl + 8) s[nt][2] = -1e30f;
                if (kcol + 1 > qrl + 8) s[nt][3] = -1e30f;
            }
        }

        // ---- Online softmax ----
        float rl = -1e30f, rh = -1e30f;
        #pragma unroll
        for (int nt = 0; nt < 8; nt++) {
            rl = fmaxf(rl, fmaxf(s[nt][0], s[nt][1]));
            rh = fmaxf(rh, fmaxf(s[nt][2], s[nt][3]));
        }
        rl = fmaxf(rl, __shfl_xor_sync(0xffffffffu, rl, 1));
        rl = fmaxf(rl, __shfl_xor_sync(0xffffffffu, rl, 2));
        rh = fmaxf(rh, __shfl_xor_sync(0xffffffffu, rh, 1));
        rh = fmaxf(rh, __shfl_xor_sync(0xffffffffu, rh, 2));

        float mnl = fmaxf(m_lo, rl), mnh = fmaxf(m_hi, rh);
        float cl = exp2a(m_lo - mnl), ch = exp2a(m_hi - mnh);
        m_lo = mnl; m_hi = mnh;

        unsigned pb[8][4];
        float suml = 0.0f, sumh = 0.0f;
        #pragma unroll
        for (int nt = 0; nt < 8; nt++) {
            pb[nt][0] = f2tf32(exp2a(s[nt][0] - mnl));
            pb[nt][1] = f2tf32(exp2a(s[nt][1] - mnl));
            pb[nt][2] = f2tf32(exp2a(s[nt][2] - mnh));
            pb[nt][3] = f2tf32(exp2a(s[nt][3] - mnh));
            suml += __uint_as_float(pb[nt][0]) + __uint_as_float(pb[nt][1]);
            sumh += __uint_as_float(pb[nt][2]) + __uint_as_float(pb[nt][3]);
        }
        suml += __shfl_xor_sync(0xffffffffu, suml, 1);
        suml += __shfl_xor_sync(0xffffffffu, suml, 2);
        sumh += __shfl_xor_sync(0xffffffffu, sumh, 1);
        sumh += __shfl_xor_sync(0xffffffffu, sumh, 2);
        l_lo = l_lo * cl + suml;
        l_hi = l_hi * ch + sumh;

        #pragma unroll
        for (int nt = 0; nt < 8; nt++) {
            O[nt][0] *= cl; O[nt][1] *= cl;
            O[nt][2] *= ch; O[nt][3] *= ch;
        }

        __syncthreads();   // all warps done reading Kn -> safe to overwrite with P

        #pragma unroll
        for (int nt = 0; nt < 8; nt++) {
            *(uint2*)&Psp[lr * 68 + nt * 8 + 2 * lc]       = make_uint2(pb[nt][0], pb[nt][1]);
            *(uint2*)&Psp[(lr + 8) * 68 + nt * 8 + 2 * lc] = make_uint2(pb[nt][2], pb[nt][3]);
        }
        __syncwarp();

        // ---- O += P V ----
        #pragma unroll
        for (int kk8 = 0; kk8 < 8; kk8++) {
            unsigned pa[4];
            pa[0] = Psp[lr * 68 + kk8 * 8 + lc];
            pa[1] = Psp[(lr + 8) * 68 + kk8 * 8 + lc];
            pa[2] = Psp[lr * 68 + kk8 * 8 + lc + 4];
            pa[3] = Psp[(lr + 8) * 68 + kk8 * 8 + lc + 4];
            #pragma unroll
            for (int nt = 0; nt < 8; nt++) {
                unsigned bfr[2];
                bfr[0] = Vsp[(kk8 * 8 + lc) * 68 + nt * 8 + lr];
                bfr[1] = Vsp[(kk8 * 8 + lc + 4) * 68 + nt * 8 + lr];
                mma_tf32(O[nt], pa, bfr);
            }
        }
        __syncthreads();   // before next tile's cp.async overwrites this buffer
    }

    const float il = 1.0f / l_lo;
    const float ih = 1.0f / l_hi;
    float* ylo = y + (bT + q0 + qrl) * CC + h * DD;
    float* yhi = ylo + (size_t)8 * CC;
    #pragma unroll
    for (int nt = 0; nt < 8; nt++) {
        int c0 = nt * 8 + 2 * lc;
        *(float2*)&ylo[c0] = make_float2(rnd_tf32(O[nt][0] * il), rnd_tf32(O[nt][1] * il));
        *(float2*)&yhi[c0] = make_float2(rnd_tf32(O[nt][2] * ih), rnd_tf32(O[nt][3] * ih));
    }
}

// ---------------------------------------------------------------------------
// Launch
// ---------------------------------------------------------------------------
extern "C" void kernel_launch(void* const* d_in, const int* in_sizes, int n_in,
                              void* d_out, int out_size)
{
    const float* x      = (const float*)d_in[0];
    const float* w_qkv  = (const float*)d_in[1];
    const float* b_qkv  = (const float*)d_in[2];
    const float* w_proj = (const float*)d_in[3];
    const float* b_proj = (const float*)d_in[4];
    float* out = (float*)d_out;

    float *qkv, *y, *xp, *yp, *wqkvp, *wprojp;
    cudaGetSymbolAddress((void**)&qkv,    g_qkv);
    cudaGetSymbolAddress((void**)&y,      g_y);
    cudaGetSymbolAddress((void**)&xp,     g_xp);
    cudaGetSymbolAddress((void**)&yp,     g_yp);
    cudaGetSymbolAddress((void**)&wqkvp,  g_wqkvp);
    cudaGetSymbolAddress((void**)&wprojp, g_wprojp);

    cudaFuncSetAttribute(gemm_pipe<true>,  cudaFuncAttributeMaxDynamicSharedMemorySize, GSM_BYTES);
    cudaFuncSetAttribute(gemm_pipe<false>, cudaFuncAttributeMaxDynamicSharedMemorySize, GSM_BYTES);
    cudaFuncSetAttribute(attn_mma, cudaFuncAttributeMaxDynamicSharedMemorySize, ASM_BYTES);

    // 0) Permute + round inputs
    {
        int nA = M_ROWS * CC;
        permute_a_kernel<<<(nA + 255) / 256, 256>>>(x, xp, CC, nA);
        int nB1 = CC * N_QKV;
        permute_b_kernel<<<(nB1 + 255) / 256, 256>>>(w_qkv, wqkvp, N_QKV, CC, nB1);
        int nB2 = CC * CC;
        permute_b_kernel<<<(nB2 + 255) / 256, 256>>>(w_proj, wprojp, CC, CC, nB2);
    }

    // 1) QKV projection (epilogue rounds to tf32 for attention consumption)
    gemm_pipe<true><<<dim3(N_QKV / 128, M_ROWS / 128), 256, GSM_BYTES>>>(
        xp, wqkvp, b_qkv, qkv, N_QKV, CC);

    // 2) Causal attention
    attn_mma<<<dim3(TT / 64, BB * HH), 128, ASM_BYTES>>>(qkv, y);

    // 2.5) Permute y for the output projection
    {
        int nA = M_ROWS * CC;
        permute_a_kernel<<<(nA + 255) / 256, 256>>>(y, yp, CC, nA);
    }

    // 3) Output projection (no rounding on final output)
    gemm_pipe<false><<<dim3(CC / 128, M_ROWS / 128), 256, GSM_BYTES>>>(
        yp, wprojp, b_proj, out, CC, CC);
}